// round 4
// baseline (speedup 1.0000x reference)
#include <cuda_runtime.h>
#include <cstdint>

#define C_CH 32
#define DIM  128
#define NK   27
#define VOL_ELEMS (C_CH * DIM * DIM * DIM)
#define NCELL 4096            // 16x16x16 cells of 8^3 voxels
#define PERM_MAX (1 << 18)
#define TPW 8                 // vertices per warp

// Scratch (device globals: allocation-free per harness rules)
__device__ float g_vol[VOL_ELEMS];        // channel-last [z][y][x][c]
__device__ float g_G[NK * C_CH * C_CH];   // [k][j][o] folded weight tensor
__device__ float g_bias[C_CH];
__device__ int   g_hist[NCELL];
__device__ int   g_base[NCELL];
__device__ int   g_perm[PERM_MAX];

// ---------------------------------------------------------------------------
// Prep 1 (27 blocks): M[k][j][o] = sum_c conv_w[o,c,k]*Wd[c,j]
// ---------------------------------------------------------------------------
__global__ __launch_bounds__(1024) void prep1_kernel(
    const float* __restrict__ w_d1, const float* __restrict__ w_d2,
    const float* __restrict__ conv_w)
{
    __shared__ float Wds[1024];    // Wd[c][j]
    __shared__ float convs[1024];  // conv[c][o] for this k
    const int tid = threadIdx.x, k = blockIdx.x;
    const int o = tid & 31, j = tid >> 5;

    {   // Wd = w_d2 @ w_d1
        float s = 0.f;
        #pragma unroll
        for (int m = 0; m < 32; m++)
            s += w_d2[(tid >> 5) * 32 + m] * w_d1[m * 32 + (tid & 31)];
        Wds[tid] = s;
    }
    convs[tid] = conv_w[(o * 32 + (tid >> 5)) * 27 + k];
    __syncthreads();

    float acc = 0.f;
    #pragma unroll
    for (int c = 0; c < 32; c++)
        acc += convs[c * 32 + o] * Wds[c * 32 + j];
    g_G[k * 1024 + j * 32 + o] = acc;
}

// ---------------------------------------------------------------------------
// Prep 2 (1 block): center-tap correction + fused bias + zero histograms.
// ---------------------------------------------------------------------------
__global__ __launch_bounds__(1024) void prep2_kernel(
    const float* __restrict__ w_d2, const float* __restrict__ b_d1,
    const float* __restrict__ b_d2,
    const float* __restrict__ w_c1, const float* __restrict__ b_c1,
    const float* __restrict__ w_c2, const float* __restrict__ b_c2,
    const float* __restrict__ conv_w, const float* __restrict__ conv_b)
{
    __shared__ float Wcs[1024], part[1024], bds[32], bcs[32];
    const int tid = threadIdx.x;
    const int o = tid & 31, j = tid >> 5;

    // zero binning scratch (fused to save a launch)
    #pragma unroll
    for (int i = 0; i < NCELL / 1024; i++) {
        g_hist[tid + 1024 * i] = 0;
        g_base[tid + 1024 * i] = 0;
    }

    {   // Wc = w_c2 @ w_c1
        float s = 0.f;
        #pragma unroll
        for (int m = 0; m < 32; m++)
            s += w_c2[(tid >> 5) * 32 + m] * w_c1[m * 32 + (tid & 31)];
        Wcs[tid] = s;
    }
    if (tid < 32) {
        float sd = 0.f, sc = 0.f;
        #pragma unroll
        for (int m = 0; m < 32; m++) {
            sd += w_d2[tid * 32 + m] * b_d1[m];
            sc += w_c2[tid * 32 + m] * b_c1[m];
        }
        bds[tid] = sd + b_d2[tid];
        bcs[tid] = sc + b_c2[tid];
    }
    float rs = 0.f;
    #pragma unroll
    for (int k = 0; k < NK; k++)
        rs += conv_w[(o * 32 + j) * 27 + k];
    __syncthreads();

    part[j * 32 + o] = bds[j] * rs;

    float S = 0.f;
    #pragma unroll
    for (int k = 0; k < NK; k++) S += g_G[k * 1024 + tid];
    g_G[13 * 1024 + tid] += Wcs[o * 32 + j] - S;
    __syncthreads();

    if (tid < 32) {
        float a = 0.f;
        #pragma unroll
        for (int c = 0; c < 32; c++) a += part[c * 32 + tid];
        g_bias[tid] = a + conv_b[tid] + bcs[tid];
    }
}

// ---------------------------------------------------------------------------
// Transpose [C][D][H][W] -> channel-last [D][H][W][C], STG.128 stores.
// ---------------------------------------------------------------------------
__global__ __launch_bounds__(256) void transpose_kernel(const float* __restrict__ vin)
{
    __shared__ float tile[32][33];
    const int x0 = blockIdx.x * 32;
    const int y = blockIdx.y, z = blockIdx.z;
    const int tid = threadIdx.x;
    const int tx = tid & 31, ty = tid >> 5;

    #pragma unroll
    for (int i = 0; i < 4; i++) {
        const int c = ty + 8 * i;
        tile[c][tx] = vin[(((size_t)c * DIM + z) * DIM + y) * DIM + x0 + tx];
    }
    __syncthreads();

    const int q  = tid & 7;          // channel quad
    const int xl = (tid >> 3) & 3;
    const int xg = tid >> 5;
    const size_t obase = ((size_t)z * DIM + y) * DIM + x0;
    const int xx = xg * 4 + xl;
    float4 v;
    v.x = tile[4 * q + 0][xx];
    v.y = tile[4 * q + 1][xx];
    v.z = tile[4 * q + 2][xx];
    v.w = tile[4 * q + 3][xx];
    reinterpret_cast<float4*>(g_vol + (obase + xx) * C_CH)[q] = v;
}

// ---------------------------------------------------------------------------
// Vertex binning: histogram -> scan -> scatter (cells of 8^3 voxels).
// ---------------------------------------------------------------------------
__device__ __forceinline__ int cell_of(float x, float y, float z)
{
    float px = fminf(fmaxf((x + 1.f) * 63.5f, 0.f), 127.f);
    float py = fminf(fmaxf((y + 1.f) * 63.5f, 0.f), 127.f);
    float pz = fminf(fmaxf((z + 1.f) * 63.5f, 0.f), 127.f);
    const int cx = ((int)px) >> 3, cy = ((int)py) >> 3, cz = ((int)pz) >> 3;
    return (cz << 8) | (cy << 4) | cx;
}

__global__ void count_kernel(const float* __restrict__ verts, int Ntot)
{
    const int n = blockIdx.x * blockDim.x + threadIdx.x;
    if (n >= Ntot) return;
    atomicAdd(&g_hist[cell_of(verts[3 * n], verts[3 * n + 1], verts[3 * n + 2])], 1);
}

__global__ __launch_bounds__(1024) void scan_kernel()
{
    __shared__ int sh[1024];
    const int t = threadIdx.x;
    int h0 = g_hist[4 * t], h1 = g_hist[4 * t + 1],
        h2 = g_hist[4 * t + 2], h3 = g_hist[4 * t + 3];
    const int mysum = h0 + h1 + h2 + h3;
    sh[t] = mysum;
    __syncthreads();
    for (int off = 1; off < 1024; off <<= 1) {
        int v = (t >= off) ? sh[t - off] : 0;
        __syncthreads();
        sh[t] += v;
        __syncthreads();
    }
    int e = sh[t] - mysum;
    g_base[4 * t]     = e;
    g_base[4 * t + 1] = e + h0;
    g_base[4 * t + 2] = e + h0 + h1;
    g_base[4 * t + 3] = e + h0 + h1 + h2;
}

__global__ void scatter_kernel(const float* __restrict__ verts, int Ntot)
{
    const int n = blockIdx.x * blockDim.x + threadIdx.x;
    if (n >= Ntot) return;
    const int c = cell_of(verts[3 * n], verts[3 * n + 1], verts[3 * n + 2]);
    const int pos = atomicAdd(&g_base[c], 1);
    g_perm[pos] = n;
}

// ---------------------------------------------------------------------------
// Fused sample + GEMM over permuted vertices. One warp = 8 vertices
// (small tile => 2x resident warps to cover gather latency).
// Sampling lane = (vertex-quad, channel-quad), float4 corner loads.
// Reduction lane = output channel, packed fma.rn.f32x2.
// ---------------------------------------------------------------------------
__global__ __launch_bounds__(256, 4) void main_kernel(
    const float* __restrict__ verts, float* __restrict__ out, int Ntot)
{
    __shared__ float fs[8 * 32 * 10];     // per warp: f[c][v], stride 10 (8B-aligned rows)
    const int warp = threadIdx.x >> 5, lane = threadIdx.x & 31;
    const int nTiles = (Ntot + TPW - 1) / TPW;
    const int tile = blockIdx.x * 8 + warp;
    if (tile >= nTiles) return;

    const int n0 = tile * TPW;
    const int v = lane & 7;               // geometry vertex (4 copies per warp)
    const int idx = n0 + v;
    const bool valid = (idx < Ntot);
    const int n = valid ? g_perm[idx] : 0;

    float gxv = 0.f, gyv = 0.f, gzv = 0.f;
    if (valid) {
        gxv = verts[3 * n + 0];
        gyv = verts[3 * n + 1];
        gzv = verts[3 * n + 2];
    }

    const int c4 = lane & 7;              // channel quad
    const int v4 = lane >> 3;             // vertex within group of 4

    float* fw = fs + warp * (32 * 10);
    unsigned long long acc2[4];
    #pragma unroll
    for (int i = 0; i < 4; i++) acc2[i] = 0ull;

    const float SH = 0.0625f;

    for (int k = 0; k < NK; k++) {
        const int ki = k / 9, kj = (k / 3) % 3, kl = k % 3;
        float gx = gxv + (float)(ki - 1) * SH;
        float gy = gyv + (float)(kj - 1) * SH;
        float gz = gzv + (float)(kl - 1) * SH;
        float px = fminf(fmaxf((gx + 1.f) * 63.5f, 0.f), 127.f);
        float py = fminf(fmaxf((gy + 1.f) * 63.5f, 0.f), 127.f);
        float pz = fminf(fmaxf((gz + 1.f) * 63.5f, 0.f), 127.f);
        const float fx = floorf(px), fy = floorf(py), fz = floorf(pz);
        const int ix = (int)fx, iy = (int)fy, iz = (int)fz;
        const float wx = px - fx, wy = py - fy, wz = pz - fz;
        const int base = iz * (DIM * DIM * C_CH) + iy * (DIM * C_CH) + ix * C_CH;
        const int sx = (ix < DIM - 1) ? C_CH : 0;
        const int sy = (iy < DIM - 1) ? DIM * C_CH : 0;
        const int sz = (iz < DIM - 1) ? DIM * DIM * C_CH : 0;

        #pragma unroll
        for (int g4 = 0; g4 < 2; g4++) {
            const int src = g4 * 4 + v4;
            const int b   = __shfl_sync(0xffffffffu, base, src);
            const int sx4 = __shfl_sync(0xffffffffu, sx, src) >> 2;
            const int sy4 = __shfl_sync(0xffffffffu, sy, src) >> 2;
            const int sz4 = __shfl_sync(0xffffffffu, sz, src) >> 2;
            const float wxv = __shfl_sync(0xffffffffu, wx, src);
            const float wyv = __shfl_sync(0xffffffffu, wy, src);
            const float wzv = __shfl_sync(0xffffffffu, wz, src);

            const float4* p = reinterpret_cast<const float4*>(g_vol + b) + c4;
            const float4 f000 = __ldg(p);
            const float4 f001 = __ldg(p + sx4);
            const float4 f010 = __ldg(p + sy4);
            const float4 f011 = __ldg(p + sy4 + sx4);
            const float4 f100 = __ldg(p + sz4);
            const float4 f101 = __ldg(p + sz4 + sx4);
            const float4 f110 = __ldg(p + sz4 + sy4);
            const float4 f111 = __ldg(p + sz4 + sy4 + sx4);

            const float ax0 = 1.f - wxv, ay0 = 1.f - wyv, az0 = 1.f - wzv;
            const float c00 = az0 * ay0, c01 = az0 * wyv;
            const float c10 = wzv * ay0, c11 = wzv * wyv;
            const float w000 = c00 * ax0, w001 = c00 * wxv;
            const float w010 = c01 * ax0, w011 = c01 * wxv;
            const float w100 = c10 * ax0, w101 = c10 * wxv;
            const float w110 = c11 * ax0, w111 = c11 * wxv;

            float rx = f000.x * w000, ry = f000.y * w000,
                  rz = f000.z * w000, rw = f000.w * w000;
            rx = fmaf(f001.x, w001, rx); ry = fmaf(f001.y, w001, ry);
            rz = fmaf(f001.z, w001, rz); rw = fmaf(f001.w, w001, rw);
            rx = fmaf(f010.x, w010, rx); ry = fmaf(f010.y, w010, ry);
            rz = fmaf(f010.z, w010, rz); rw = fmaf(f010.w, w010, rw);
            rx = fmaf(f011.x, w011, rx); ry = fmaf(f011.y, w011, ry);
            rz = fmaf(f011.z, w011, rz); rw = fmaf(f011.w, w011, rw);
            rx = fmaf(f100.x, w100, rx); ry = fmaf(f100.y, w100, ry);
            rz = fmaf(f100.z, w100, rz); rw = fmaf(f100.w, w100, rw);
            rx = fmaf(f101.x, w101, rx); ry = fmaf(f101.y, w101, ry);
            rz = fmaf(f101.z, w101, rz); rw = fmaf(f101.w, w101, rw);
            rx = fmaf(f110.x, w110, rx); ry = fmaf(f110.y, w110, ry);
            rz = fmaf(f110.z, w110, rz); rw = fmaf(f110.w, w110, rw);
            rx = fmaf(f111.x, w111, rx); ry = fmaf(f111.y, w111, ry);
            rz = fmaf(f111.z, w111, rz); rw = fmaf(f111.w, w111, rw);

            const int col = g4 * 4 + v4;
            fw[(c4 * 4 + 0) * 10 + col] = rx;
            fw[(c4 * 4 + 1) * 10 + col] = ry;
            fw[(c4 * 4 + 2) * 10 + col] = rz;
            fw[(c4 * 4 + 3) * 10 + col] = rw;
        }
        __syncwarp();

        #pragma unroll 4
        for (int c = 0; c < 32; c++) {
            const float g = __ldg(&g_G[k * 1024 + c * 32 + lane]);
            unsigned long long g2;
            asm("mov.b64 %0, {%1, %1};" : "=l"(g2) : "r"(__float_as_uint(g)));
            const unsigned long long* fq =
                reinterpret_cast<const unsigned long long*>(fw + c * 10);
            #pragma unroll
            for (int v2 = 0; v2 < 4; v2++) {
                asm("fma.rn.f32x2 %0, %1, %2, %0;"
                    : "+l"(acc2[v2]) : "l"(fq[v2]), "l"(g2));
            }
        }
        __syncwarp();
    }

    const float bias = __ldg(&g_bias[lane]);
    #pragma unroll
    for (int v2 = 0; v2 < 4; v2++) {
        const float lo = __uint_as_float((unsigned)(acc2[v2] & 0xffffffffull));
        const float hi = __uint_as_float((unsigned)(acc2[v2] >> 32));
        const int ia = n0 + 2 * v2, ib = ia + 1;
        if (ia < Ntot) out[g_perm[ia] * C_CH + lane] = lo + bias;
        if (ib < Ntot) out[g_perm[ib] * C_CH + lane] = hi + bias;
    }
}

// ---------------------------------------------------------------------------
extern "C" void kernel_launch(void* const* d_in, const int* in_sizes, int n_in,
                              void* d_out, int out_size)
{
    const float* voxel = (const float*)d_in[0];
    const float* verts = (const float*)d_in[1];
    const int Ntot = in_sizes[1] / 3;

    prep1_kernel<<<27, 1024>>>(
        (const float*)d_in[2], (const float*)d_in[4], (const float*)d_in[10]);

    prep2_kernel<<<1, 1024>>>(
        (const float*)d_in[4], (const float*)d_in[3], (const float*)d_in[5],
        (const float*)d_in[6], (const float*)d_in[7], (const float*)d_in[8],
        (const float*)d_in[9], (const float*)d_in[10], (const float*)d_in[11]);

    count_kernel<<<(Ntot + 255) / 256, 256>>>(verts, Ntot);
    scan_kernel<<<1, 1024>>>();
    scatter_kernel<<<(Ntot + 255) / 256, 256>>>(verts, Ntot);

    dim3 tb(256);
    dim3 tg(DIM / 32, DIM, DIM);
    transpose_kernel<<<tg, tb>>>(voxel);

    const int nTiles = (Ntot + TPW - 1) / TPW;
    const int blocks = (nTiles + 7) / 8;
    main_kernel<<<blocks, 256>>>(verts, (float*)d_out, Ntot);
}

// round 5
// speedup vs baseline: 1.1922x; 1.1922x over previous
#include <cuda_runtime.h>
#include <cstdint>

#define C_CH 32
#define DIM  128
#define NK   27
#define VOL_ELEMS (C_CH * DIM * DIM * DIM)
#define NCELL 4096            // 16x16x16 cells of 8^3 voxels
#define PERM_MAX (1 << 18)
#define TPW 16                // vertices per warp (R4 showed 8 regresses)

// per-warp smem feat row offset: stride 36 + 16B pad every 8 rows
// -> rows 16B-aligned (LDS.128) AND sampling STS conflict-free
#define WREG 1168             // words per warp region (32*36+16)

// Scratch (device globals: allocation-free per harness rules)
__device__ float g_vol[VOL_ELEMS];                  // channel-last [z][y][x][c]
__device__ float g_G[NK * C_CH * C_CH];             // [k][j][o] folded weights
__device__ unsigned long long g_G2[NK * C_CH * C_CH]; // duplicated {g,g} pairs
__device__ float g_bias[C_CH];
__device__ int   g_hist[NCELL];
__device__ int   g_base[NCELL];
__device__ int   g_perm[PERM_MAX];

// ---------------------------------------------------------------------------
// Prep 1 (27 blocks): M[k][j][o] = sum_c conv_w[o,c,k]*Wd[c,j]
// ---------------------------------------------------------------------------
__global__ __launch_bounds__(1024) void prep1_kernel(
    const float* __restrict__ w_d1, const float* __restrict__ w_d2,
    const float* __restrict__ conv_w)
{
    __shared__ float Wds[1024];    // Wd[c][j]
    __shared__ float convs[1024];  // conv[c][o] for this k
    const int tid = threadIdx.x, k = blockIdx.x;
    const int o = tid & 31, j = tid >> 5;

    {   // Wd = w_d2 @ w_d1
        float s = 0.f;
        #pragma unroll
        for (int m = 0; m < 32; m++)
            s += w_d2[(tid >> 5) * 32 + m] * w_d1[m * 32 + (tid & 31)];
        Wds[tid] = s;
    }
    convs[tid] = conv_w[(o * 32 + (tid >> 5)) * 27 + k];
    __syncthreads();

    float acc = 0.f;
    #pragma unroll
    for (int c = 0; c < 32; c++)
        acc += convs[c * 32 + o] * Wds[c * 32 + j];
    g_G[k * 1024 + j * 32 + o] = acc;
}

// ---------------------------------------------------------------------------
// Prep 2 (1 block): center-tap correction + fused bias + zero histograms
// + build duplicated-pair table g_G2.
// ---------------------------------------------------------------------------
__global__ __launch_bounds__(1024) void prep2_kernel(
    const float* __restrict__ w_d2, const float* __restrict__ b_d1,
    const float* __restrict__ b_d2,
    const float* __restrict__ w_c1, const float* __restrict__ b_c1,
    const float* __restrict__ w_c2, const float* __restrict__ b_c2,
    const float* __restrict__ conv_w, const float* __restrict__ conv_b)
{
    __shared__ float Wcs[1024], part[1024], bds[32], bcs[32];
    const int tid = threadIdx.x;
    const int o = tid & 31, j = tid >> 5;

    #pragma unroll
    for (int i = 0; i < NCELL / 1024; i++) {
        g_hist[tid + 1024 * i] = 0;
        g_base[tid + 1024 * i] = 0;
    }

    {   // Wc = w_c2 @ w_c1
        float s = 0.f;
        #pragma unroll
        for (int m = 0; m < 32; m++)
            s += w_c2[(tid >> 5) * 32 + m] * w_c1[m * 32 + (tid & 31)];
        Wcs[tid] = s;
    }
    if (tid < 32) {
        float sd = 0.f, sc = 0.f;
        #pragma unroll
        for (int m = 0; m < 32; m++) {
            sd += w_d2[tid * 32 + m] * b_d1[m];
            sc += w_c2[tid * 32 + m] * b_c1[m];
        }
        bds[tid] = sd + b_d2[tid];
        bcs[tid] = sc + b_c2[tid];
    }
    float rs = 0.f;
    #pragma unroll
    for (int k = 0; k < NK; k++)
        rs += conv_w[(o * 32 + j) * 27 + k];
    __syncthreads();

    part[j * 32 + o] = bds[j] * rs;

    float S = 0.f;
    #pragma unroll
    for (int k = 0; k < NK; k++) S += g_G[k * 1024 + tid];
    g_G[13 * 1024 + tid] += Wcs[o * 32 + j] - S;

    // duplicated-pair table (k=13 written by this same thread above -> visible)
    for (int k = 0; k < NK; k++) {
        const unsigned u = __float_as_uint(g_G[k * 1024 + tid]);
        g_G2[k * 1024 + tid] = (unsigned long long)u |
                               ((unsigned long long)u << 32);
    }
    __syncthreads();

    if (tid < 32) {
        float a = 0.f;
        #pragma unroll
        for (int c = 0; c < 32; c++) a += part[c * 32 + tid];
        g_bias[tid] = a + conv_b[tid] + bcs[tid];
    }
}

// ---------------------------------------------------------------------------
// Transpose [C][D][H][W] -> channel-last [D][H][W][C], STG.128 stores.
// ---------------------------------------------------------------------------
__global__ __launch_bounds__(256) void transpose_kernel(const float* __restrict__ vin)
{
    __shared__ float tile[32][33];
    const int x0 = blockIdx.x * 32;
    const int y = blockIdx.y, z = blockIdx.z;
    const int tid = threadIdx.x;
    const int tx = tid & 31, ty = tid >> 5;

    #pragma unroll
    for (int i = 0; i < 4; i++) {
        const int c = ty + 8 * i;
        tile[c][tx] = vin[(((size_t)c * DIM + z) * DIM + y) * DIM + x0 + tx];
    }
    __syncthreads();

    const int q  = tid & 7;          // channel quad
    const int xl = (tid >> 3) & 3;
    const int xg = tid >> 5;
    const size_t obase = ((size_t)z * DIM + y) * DIM + x0;
    const int xx = xg * 4 + xl;
    float4 v;
    v.x = tile[4 * q + 0][xx];
    v.y = tile[4 * q + 1][xx];
    v.z = tile[4 * q + 2][xx];
    v.w = tile[4 * q + 3][xx];
    reinterpret_cast<float4*>(g_vol + (obase + xx) * C_CH)[q] = v;
}

// ---------------------------------------------------------------------------
// Vertex binning: histogram -> scan -> scatter (cells of 8^3 voxels).
// ---------------------------------------------------------------------------
__device__ __forceinline__ int cell_of(float x, float y, float z)
{
    float px = fminf(fmaxf((x + 1.f) * 63.5f, 0.f), 127.f);
    float py = fminf(fmaxf((y + 1.f) * 63.5f, 0.f), 127.f);
    float pz = fminf(fmaxf((z + 1.f) * 63.5f, 0.f), 127.f);
    const int cx = ((int)px) >> 3, cy = ((int)py) >> 3, cz = ((int)pz) >> 3;
    return (cz << 8) | (cy << 4) | cx;
}

__global__ void count_kernel(const float* __restrict__ verts, int Ntot)
{
    const int n = blockIdx.x * blockDim.x + threadIdx.x;
    if (n >= Ntot) return;
    atomicAdd(&g_hist[cell_of(verts[3 * n], verts[3 * n + 1], verts[3 * n + 2])], 1);
}

__global__ __launch_bounds__(1024) void scan_kernel()
{
    __shared__ int sh[1024];
    const int t = threadIdx.x;
    int h0 = g_hist[4 * t], h1 = g_hist[4 * t + 1],
        h2 = g_hist[4 * t + 2], h3 = g_hist[4 * t + 3];
    const int mysum = h0 + h1 + h2 + h3;
    sh[t] = mysum;
    __syncthreads();
    for (int off = 1; off < 1024; off <<= 1) {
        int v = (t >= off) ? sh[t - off] : 0;
        __syncthreads();
        sh[t] += v;
        __syncthreads();
    }
    int e = sh[t] - mysum;
    g_base[4 * t]     = e;
    g_base[4 * t + 1] = e + h0;
    g_base[4 * t + 2] = e + h0 + h1;
    g_base[4 * t + 3] = e + h0 + h1 + h2;
}

__global__ void scatter_kernel(const float* __restrict__ verts, int Ntot)
{
    const int n = blockIdx.x * blockDim.x + threadIdx.x;
    if (n >= Ntot) return;
    const int c = cell_of(verts[3 * n], verts[3 * n + 1], verts[3 * n + 2]);
    const int pos = atomicAdd(&g_base[c], 1);
    g_perm[pos] = n;
}

// ---------------------------------------------------------------------------
// Fused sample + GEMM over permuted vertices. One warp = 16 vertices.
// Sampling lane = (vertex-quad, channel-quad), float4 corner loads;
// feats staged in padded smem (conflict-free STS, 16B-aligned rows).
// Reduction lane = output channel: LDG.64 of pre-duplicated G + LDS.128
// feat reads + packed fma.rn.f32x2 over vertex pairs.
// ---------------------------------------------------------------------------
__global__ __launch_bounds__(256, 3) void main_kernel(
    const float* __restrict__ verts, float* __restrict__ out, int Ntot)
{
    __shared__ __align__(16) float fs[8 * WREG];
    const int warp = threadIdx.x >> 5, lane = threadIdx.x & 31;
    const int nTiles = (Ntot + TPW - 1) / TPW;
    const int tile = blockIdx.x * 8 + warp;
    if (tile >= nTiles) return;

    const int n0 = tile * TPW;
    const int v = lane & 15;
    const int idx = n0 + v;
    const bool valid = (idx < Ntot);
    const int n = valid ? g_perm[idx] : 0;

    float gxv = 0.f, gyv = 0.f, gzv = 0.f;
    if (valid) {
        gxv = verts[3 * n + 0];
        gyv = verts[3 * n + 1];
        gzv = verts[3 * n + 2];
    }

    const int c4 = lane & 7;              // channel quad
    const int v4 = lane >> 3;             // vertex within group of 4
    // row base for this lane's 4 channel rows: OFF(4*c4) = 144*c4 + 4*(c4>>1)
    const int rowbase = 144 * c4 + ((c4 >> 1) << 2);

    float* fw = fs + warp * WREG;
    unsigned long long acc2[8];
    #pragma unroll
    for (int i = 0; i < 8; i++) acc2[i] = 0ull;

    const float SH = 0.0625f;

    #pragma unroll 1
    for (int k = 0; k < NK; k++) {
        const int ki = k / 9, kj = (k / 3) % 3, kl = k % 3;
        float gx = gxv + (float)(ki - 1) * SH;
        float gy = gyv + (float)(kj - 1) * SH;
        float gz = gzv + (float)(kl - 1) * SH;
        float px = fminf(fmaxf((gx + 1.f) * 63.5f, 0.f), 127.f);
        float py = fminf(fmaxf((gy + 1.f) * 63.5f, 0.f), 127.f);
        float pz = fminf(fmaxf((gz + 1.f) * 63.5f, 0.f), 127.f);
        const float fx = floorf(px), fy = floorf(py), fz = floorf(pz);
        const int ix = (int)fx, iy = (int)fy, iz = (int)fz;
        const float wx = px - fx, wy = py - fy, wz = pz - fz;
        const int base = iz * (DIM * DIM * C_CH) + iy * (DIM * C_CH) + ix * C_CH;
        const int sx = (ix < DIM - 1) ? C_CH : 0;
        const int sy = (iy < DIM - 1) ? DIM * C_CH : 0;
        const int sz = (iz < DIM - 1) ? DIM * DIM * C_CH : 0;

        #pragma unroll
        for (int g4 = 0; g4 < 4; g4++) {
            const int src = g4 * 4 + v4;
            const int b   = __shfl_sync(0xffffffffu, base, src);
            const int sx4 = __shfl_sync(0xffffffffu, sx, src) >> 2;
            const int sy4 = __shfl_sync(0xffffffffu, sy, src) >> 2;
            const int sz4 = __shfl_sync(0xffffffffu, sz, src) >> 2;
            const float wxv = __shfl_sync(0xffffffffu, wx, src);
            const float wyv = __shfl_sync(0xffffffffu, wy, src);
            const float wzv = __shfl_sync(0xffffffffu, wz, src);

            const float4* p = reinterpret_cast<const float4*>(g_vol + b) + c4;
            const float4 f000 = __ldg(p);
            const float4 f001 = __ldg(p + sx4);
            const float4 f010 = __ldg(p + sy4);
            const float4 f011 = __ldg(p + sy4 + sx4);
            const float4 f100 = __ldg(p + sz4);
            const float4 f101 = __ldg(p + sz4 + sx4);
            const float4 f110 = __ldg(p + sz4 + sy4);
            const float4 f111 = __ldg(p + sz4 + sy4 + sx4);

            const float ax0 = 1.f - wxv, ay0 = 1.f - wyv, az0 = 1.f - wzv;
            const float c00 = az0 * ay0, c01 = az0 * wyv;
            const float c10 = wzv * ay0, c11 = wzv * wyv;
            const float w000 = c00 * ax0, w001 = c00 * wxv;
            const float w010 = c01 * ax0, w011 = c01 * wxv;
            const float w100 = c10 * ax0, w101 = c10 * wxv;
            const float w110 = c11 * ax0, w111 = c11 * wxv;

            float rx = f000.x * w000, ry = f000.y * w000,
                  rz = f000.z * w000, rw = f000.w * w000;
            rx = fmaf(f001.x, w001, rx); ry = fmaf(f001.y, w001, ry);
            rz = fmaf(f001.z, w001, rz); rw = fmaf(f001.w, w001, rw);
            rx = fmaf(f010.x, w010, rx); ry = fmaf(f010.y, w010, ry);
            rz = fmaf(f010.z, w010, rz); rw = fmaf(f010.w, w010, rw);
            rx = fmaf(f011.x, w011, rx); ry = fmaf(f011.y, w011, ry);
            rz = fmaf(f011.z, w011, rz); rw = fmaf(f011.w, w011, rw);
            rx = fmaf(f100.x, w100, rx); ry = fmaf(f100.y, w100, ry);
            rz = fmaf(f100.z, w100, rz); rw = fmaf(f100.w, w100, rw);
            rx = fmaf(f101.x, w101, rx); ry = fmaf(f101.y, w101, ry);
            rz = fmaf(f101.z, w101, rz); rw = fmaf(f101.w, w101, rw);
            rx = fmaf(f110.x, w110, rx); ry = fmaf(f110.y, w110, ry);
            rz = fmaf(f110.z, w110, rz); rw = fmaf(f110.w, w110, rw);
            rx = fmaf(f111.x, w111, rx); ry = fmaf(f111.y, w111, ry);
            rz = fmaf(f111.z, w111, rz); rw = fmaf(f111.w, w111, rw);

            const int col = g4 * 4 + v4;
            fw[rowbase +   0 + col] = rx;
            fw[rowbase +  36 + col] = ry;
            fw[rowbase +  72 + col] = rz;
            fw[rowbase + 108 + col] = rw;
        }
        __syncwarp();

        // reduction: acc[v][lane] += f[v][c] * G[k][c][lane]
        const unsigned long long* gk = g_G2 + k * 1024 + lane;
        #pragma unroll
        for (int c = 0; c < 32; c++) {
            const unsigned long long g2 = __ldg(gk + c * 32);
            const ulonglong2* fq = reinterpret_cast<const ulonglong2*>(
                fw + (c * 36 + ((c >> 3) << 2)));
            const ulonglong2 q0 = fq[0];
            const ulonglong2 q1 = fq[1];
            const ulonglong2 q2 = fq[2];
            const ulonglong2 q3 = fq[3];
            asm("fma.rn.f32x2 %0, %1, %2, %0;" : "+l"(acc2[0]) : "l"(q0.x), "l"(g2));
            asm("fma.rn.f32x2 %0, %1, %2, %0;" : "+l"(acc2[1]) : "l"(q0.y), "l"(g2));
            asm("fma.rn.f32x2 %0, %1, %2, %0;" : "+l"(acc2[2]) : "l"(q1.x), "l"(g2));
            asm("fma.rn.f32x2 %0, %1, %2, %0;" : "+l"(acc2[3]) : "l"(q1.y), "l"(g2));
            asm("fma.rn.f32x2 %0, %1, %2, %0;" : "+l"(acc2[4]) : "l"(q2.x), "l"(g2));
            asm("fma.rn.f32x2 %0, %1, %2, %0;" : "+l"(acc2[5]) : "l"(q2.y), "l"(g2));
            asm("fma.rn.f32x2 %0, %1, %2, %0;" : "+l"(acc2[6]) : "l"(q3.x), "l"(g2));
            asm("fma.rn.f32x2 %0, %1, %2, %0;" : "+l"(acc2[7]) : "l"(q3.y), "l"(g2));
        }
        __syncwarp();
    }

    const float bias = __ldg(&g_bias[lane]);
    #pragma unroll
    for (int v2 = 0; v2 < 8; v2++) {
        const float lo = __uint_as_float((unsigned)(acc2[v2] & 0xffffffffull));
        const float hi = __uint_as_float((unsigned)(acc2[v2] >> 32));
        const int ia = n0 + 2 * v2, ib = ia + 1;
        if (ia < Ntot) out[g_perm[ia] * C_CH + lane] = lo + bias;
        if (ib < Ntot) out[g_perm[ib] * C_CH + lane] = hi + bias;
    }
}

// ---------------------------------------------------------------------------
extern "C" void kernel_launch(void* const* d_in, const int* in_sizes, int n_in,
                              void* d_out, int out_size)
{
    const float* voxel = (const float*)d_in[0];
    const float* verts = (const float*)d_in[1];
    const int Ntot = in_sizes[1] / 3;

    prep1_kernel<<<27, 1024>>>(
        (const float*)d_in[2], (const float*)d_in[4], (const float*)d_in[10]);

    prep2_kernel<<<1, 1024>>>(
        (const float*)d_in[4], (const float*)d_in[3], (const float*)d_in[5],
        (const float*)d_in[6], (const float*)d_in[7], (const float*)d_in[8],
        (const float*)d_in[9], (const float*)d_in[10], (const float*)d_in[11]);

    count_kernel<<<(Ntot + 255) / 256, 256>>>(verts, Ntot);
    scan_kernel<<<1, 1024>>>();
    scatter_kernel<<<(Ntot + 255) / 256, 256>>>(verts, Ntot);

    dim3 tb(256);
    dim3 tg(DIM / 32, DIM, DIM);
    transpose_kernel<<<tg, tb>>>(voxel);

    const int nTiles = (Ntot + TPW - 1) / TPW;
    const int blocks = (nTiles + 7) / 8;
    main_kernel<<<blocks, 256>>>(verts, (float*)d_out, Ntot);
}